// round 3
// baseline (speedup 1.0000x reference)
#include <cuda_runtime.h>
#include <cstdint>
#include <cstddef>

// Problem constants (fixed shapes from reference setup_inputs)
#define MROWS   8192          // B*S = 4*2048
#define INDIM   4096
#define OUTDIM  4096
#define RANK    8
#define NTHR    512
#define MTILE   2             // rows per tile
#define NG_IN   (INDIM/4)     // 1024 float4 groups per row
#define NG_OUT  (OUTDIM/4)    // 1024
#define GPT     (NG_IN/NTHR)  // 2 groups per thread
#define NTILES  (MROWS/MTILE) // 4096

__constant__ float c_nf4[16] = {
    -1.0f, -0.6961928009986877f, -0.5250730514526367f, -0.39491748809814453f,
    -0.28444138169288635f, -0.18477343022823334f, -0.09105003625154495f, 0.0f,
    0.07958029955625534f, 0.16093020141124725f, 0.24611230194568634f,
    0.33791524171829224f, 0.44070982933044434f, 0.5626170039176941f,
    0.7229568362236328f, 1.0f};

// Dequantized weights (scratch; __device__ globals per allocation rules)
__device__ __align__(16) float g_WA[RANK * INDIM];    // [r][i]
__device__ __align__(16) float g_WBt[RANK * OUTDIM];  // [r][o], pre-scaled by 4.0

__global__ void dequantA_kernel(const int* __restrict__ codes,
                                const float* __restrict__ absmax) {
    int i = blockIdx.x * blockDim.x + threadIdx.x;
    if (i < RANK * INDIM)
        g_WA[i] = c_nf4[codes[i] & 15] * absmax[i >> 6];
}

__global__ void dequantB_kernel(const int* __restrict__ codes,
                                const float* __restrict__ absmax) {
    int i = blockIdx.x * blockDim.x + threadIdx.x;
    if (i < OUTDIM * RANK) {
        int o = i >> 3;
        int r = i & 7;
        // fold SCALING = 32/8 = 4.0 into W_B; store transposed [r][o]
        g_WBt[r * OUTDIM + o] = 4.0f * c_nf4[codes[i] & 15] * absmax[i >> 6];
    }
}

// smem layout (float offsets)
#define S_WA   0
#define S_X    (RANK * INDIM)                 // 32768
#define S_RED  (S_X + 2 * MTILE * INDIM)      // 49152 (16 warps x 16 floats)
#define S_INT  (S_RED + 16 * 16)              // 49408 (MTILE*RANK = 16 floats)
#define S_TOTF (S_INT + 16)                   // 49424 floats
#define SMEM_BYTES (S_TOTF * 4)               // 197696 B

__device__ __forceinline__ void cp_async16(uint32_t saddr, const void* gptr) {
    asm volatile("cp.async.cg.shared.global [%0], [%1], 16;\n"
                 :: "r"(saddr), "l"(gptr));
}

__global__ void __launch_bounds__(NTHR, 1)
qlora_fused_kernel(const float* __restrict__ x, float* __restrict__ out) {
    extern __shared__ float smem[];
    float4* sWA4 = (float4*)(smem + S_WA);
    float4* sX4  = (float4*)(smem + S_X);
    float*  sRed = smem + S_RED;
    float*  sInt = smem + S_INT;

    const int tid = threadIdx.x;

    // ---- stage dequantized W_A into smem (8192 float4s, coalesced) ----
    const float4* gWA4 = (const float4*)g_WA;
    #pragma unroll
    for (int k = 0; k < (RANK * NG_IN) / NTHR; k++)   // 16 iters
        sWA4[tid + k * NTHR] = gWA4[tid + k * NTHR];

    // ---- W_B into registers: wbv[og][r] = WBt[r][4g..4g+3] ----
    float4 wbv[GPT][RANK];
    const float4* gWB4 = (const float4*)g_WBt;
    #pragma unroll
    for (int og = 0; og < GPT; og++) {
        int g = tid + og * NTHR;
        #pragma unroll
        for (int r = 0; r < RANK; r++)
            wbv[og][r] = gWB4[r * NG_OUT + g];
    }

    uint32_t sx_base = (uint32_t)__cvta_generic_to_shared((void*)sX4);

    // ---- prologue: prefetch first tile into buffer 0 ----
    int tt = blockIdx.x;
    if (tt < NTILES) {
        const float* src = x + (size_t)tt * (MTILE * INDIM);
        #pragma unroll
        for (int k = 0; k < (MTILE * NG_IN) / NTHR; k++) {  // 4 iters
            int idx = tid + k * NTHR;
            cp_async16(sx_base + idx * 16, src + idx * 4);
        }
    }
    asm volatile("cp.async.commit_group;\n" ::: "memory");
    __syncthreads();   // W_A staging visible before first use

    int buf = 0;
    for (; tt < NTILES; tt += gridDim.x) {
        // prefetch next tile into the other buffer
        int ttn = tt + gridDim.x;
        if (ttn < NTILES) {
            const float* src = x + (size_t)ttn * (MTILE * INDIM);
            uint32_t dst = sx_base + (uint32_t)((buf ^ 1) * (MTILE * INDIM * 4));
            #pragma unroll
            for (int k = 0; k < (MTILE * NG_IN) / NTHR; k++) {
                int idx = tid + k * NTHR;
                cp_async16(dst + idx * 16, src + idx * 4);
            }
        }
        asm volatile("cp.async.commit_group;\n" ::: "memory");
        asm volatile("cp.async.wait_group 1;\n" ::: "memory");
        __syncthreads();   // current buffer complete for all threads

        // ---- phase 1: partial dot products for MTILE rows x RANK ----
        const float4* xb = sX4 + buf * (MTILE * NG_IN);
        float acc[MTILE][RANK];
        #pragma unroll
        for (int m = 0; m < MTILE; m++)
            #pragma unroll
            for (int r = 0; r < RANK; r++)
                acc[m][r] = 0.0f;

        #pragma unroll
        for (int k = 0; k < GPT; k++) {
            int g = tid + k * NTHR;
            float4 x0 = xb[g];
            float4 x1 = xb[NG_IN + g];
            #pragma unroll
            for (int r = 0; r < RANK; r++) {
                float4 w = sWA4[r * NG_IN + g];
                acc[0][r] += x0.x * w.x + x0.y * w.y + x0.z * w.z + x0.w * w.w;
                acc[1][r] += x1.x * w.x + x1.y * w.y + x1.z * w.z + x1.w * w.w;
            }
        }

        // ---- warp butterfly reduce (16 quantities) ----
        #pragma unroll
        for (int m = 0; m < MTILE; m++)
            #pragma unroll
            for (int r = 0; r < RANK; r++) {
                float v = acc[m][r];
                v += __shfl_xor_sync(0xffffffffu, v, 16);
                v += __shfl_xor_sync(0xffffffffu, v, 8);
                v += __shfl_xor_sync(0xffffffffu, v, 4);
                v += __shfl_xor_sync(0xffffffffu, v, 2);
                v += __shfl_xor_sync(0xffffffffu, v, 1);
                acc[m][r] = v;
            }
        int lane = tid & 31;
        int wid  = tid >> 5;
        if (lane == 0) {
            float4* dst = (float4*)(sRed + wid * 16);
            dst[0] = make_float4(acc[0][0], acc[0][1], acc[0][2], acc[0][3]);
            dst[1] = make_float4(acc[0][4], acc[0][5], acc[0][6], acc[0][7]);
            dst[2] = make_float4(acc[1][0], acc[1][1], acc[1][2], acc[1][3]);
            dst[3] = make_float4(acc[1][4], acc[1][5], acc[1][6], acc[1][7]);
        }
        __syncthreads();
        if (tid < MTILE * RANK) {   // 16 threads finish cross-warp reduce
            float s = 0.0f;
            #pragma unroll
            for (int w = 0; w < NTHR / 32; w++)
                s += sRed[w * 16 + tid];
            sInt[tid] = s;
        }
        __syncthreads();

        // ---- phase 2: rank-8 epilogue from registers, coalesced stores ----
        float4 im0 = ((const float4*)sInt)[0];
        float4 im1 = ((const float4*)sInt)[1];
        float4 im2 = ((const float4*)sInt)[2];
        float4 im3 = ((const float4*)sInt)[3];
        float im[MTILE][RANK] = {
            { im0.x, im0.y, im0.z, im0.w, im1.x, im1.y, im1.z, im1.w },
            { im2.x, im2.y, im2.z, im2.w, im3.x, im3.y, im3.z, im3.w }
        };

        #pragma unroll
        for (int m = 0; m < MTILE; m++) {
            size_t rowbase = (size_t)(tt * MTILE + m) * NG_OUT;  // float4 units
            #pragma unroll
            for (int og = 0; og < GPT; og++) {
                int g = tid + og * NTHR;
                float4 o4 = make_float4(0.f, 0.f, 0.f, 0.f);
                #pragma unroll
                for (int r = 0; r < RANK; r++) {
                    float s = im[m][r];
                    float4 w = wbv[og][r];
                    o4.x += s * w.x;
                    o4.y += s * w.y;
                    o4.z += s * w.z;
                    o4.w += s * w.w;
                }
                ((float4*)out)[rowbase + g] = o4;
            }
        }

        buf ^= 1;
    }
}

extern "C" void kernel_launch(void* const* d_in, const int* in_sizes, int n_in,
                              void* d_out, int out_size) {
    const float* x         = (const float*)d_in[0];
    const int*   codes_A   = (const int*)d_in[1];
    const float* absmax_A  = (const float*)d_in[2];
    const int*   codes_B   = (const int*)d_in[3];
    const float* absmax_B  = (const float*)d_in[4];
    float*       out       = (float*)d_out;
    (void)in_sizes; (void)n_in; (void)out_size;

    // tiny dequant kernels (32768 elements each)
    dequantA_kernel<<<(RANK * INDIM + 255) / 256, 256>>>(codes_A, absmax_A);
    dequantB_kernel<<<(OUTDIM * RANK + 255) / 256, 256>>>(codes_B, absmax_B);

    // persistent fused kernel: exactly one CTA per SM (193 KB smem/CTA)
    int dev = 0, nsm = 148;
    cudaGetDevice(&dev);
    cudaDeviceGetAttribute(&nsm, cudaDevAttrMultiProcessorCount, dev);

    cudaFuncSetAttribute(qlora_fused_kernel,
                         cudaFuncAttributeMaxDynamicSharedMemorySize, SMEM_BYTES);
    qlora_fused_kernel<<<nsm, NTHR, SMEM_BYTES>>>(x, out);
}

// round 5
// speedup vs baseline: 1.0264x; 1.0264x over previous
#include <cuda_runtime.h>
#include <cstdint>
#include <cstddef>

// Fixed problem shapes
#define MROWS  8192           // B*S
#define INDIM  4096
#define OUTDIM 4096
#define RANK   8
#define NTHR   512            // 16 warps
#define TROWS  32             // rows per tile (lane = row)
#define NTILE  (MROWS/TROWS)  // 256
#define ICH    512            // i-chunk size
#define NCH    (INDIM/ICH)    // 8
#define XSTR   516            // padded floats per row in smem (conflict-free column reads)
#define XBUF   (TROWS*XSTR)   // 16512 floats per x buffer
#define WBUF   (RANK*ICH)     // 4096 floats per w buffer

// smem layout (float offsets)
#define S_X    0                              // 2 x 16512
#define S_W    (2*XBUF)                       // 33024: 2 x 4096
#define S_RED  (S_W + 2*WBUF)                 // 41216: 16 warps x 32 rows x 8
#define S_INT  (S_RED + 16*TROWS*RANK)        // 45312: 32 x 8
#define S_NF4  (S_INT + TROWS*RANK)           // 45568
#define S_TOT  (S_NF4 + 16)                   // 45584 floats
#define SMEM_BYTES (S_TOT*4)                  // 182336 B

__constant__ float c_nf4[16] = {
    -1.0f, -0.6961928009986877f, -0.5250730514526367f, -0.39491748809814453f,
    -0.28444138169288635f, -0.18477343022823334f, -0.09105003625154495f, 0.0f,
    0.07958029955625534f, 0.16093020141124725f, 0.24611230194568634f,
    0.33791524171829224f, 0.44070982933044434f, 0.5626170039176941f,
    0.7229568362236328f, 1.0f};

__device__ __forceinline__ void cp_async16(uint32_t saddr, const void* gptr) {
    asm volatile("cp.async.cg.shared.global [%0], [%1], 16;\n"
                 :: "r"(saddr), "l"(gptr));
}
__device__ __forceinline__ void fma2(unsigned long long& d,
                                     unsigned long long a, unsigned long long b) {
    asm("fma.rn.f32x2 %0, %1, %2, %0;" : "+l"(d) : "l"(a), "l"(b));
}
__device__ __forceinline__ unsigned long long pk2(float v) {
    unsigned long long r; asm("mov.b64 %0, {%1, %1};" : "=l"(r) : "f"(v)); return r;
}
__device__ __forceinline__ unsigned long long pkab(float a, float b) {
    unsigned long long r; asm("mov.b64 %0, {%1, %2};" : "=l"(r) : "f"(a), "f"(b)); return r;
}
__device__ __forceinline__ float2 unpk(unsigned long long v) {
    float2 f; asm("mov.b64 {%0, %1}, %2;" : "=f"(f.x), "=f"(f.y) : "l"(v)); return f;
}

// Producer: cp.async the x chunk + dequantize the matching W_A chunk into buffer bb.
__device__ __forceinline__ void issue_chunk(
    float* sm, uint32_t sxb, const float* __restrict__ x,
    const int* __restrict__ codesA, const float* __restrict__ absmaxA,
    int tile, int ch, int bb, int tid)
{
    if (tile >= NTILE) return;
    // x chunk: 32 rows x 512 floats = 4096 float4, 8 per thread (coalesced)
    const float* src = x + (size_t)tile * TROWS * INDIM + (size_t)ch * ICH;
    #pragma unroll
    for (int k = 0; k < 8; k++) {
        int idx = tid + k * NTHR;
        int row = idx >> 7, c4 = idx & 127;
        cp_async16(sxb + (uint32_t)((bb * XBUF + row * XSTR + c4 * 4) * 4),
                   src + (size_t)row * INDIM + c4 * 4);
    }
    // W_A chunk dequant: 8 consecutive elements per thread
    {
        int e0  = tid * 8;
        int r   = e0 >> 9;            // rank row
        int il0 = e0 & 511;           // local i
        int gb  = r * INDIM + ch * ICH + il0;
        const int4* cp = (const int4*)(codesA + gb);
        int4 ca = cp[0], cb = cp[1];
        float am = __ldg(absmaxA + (gb >> 6));  // all 8 elems share one block
        const float* nf = sm + S_NF4;
        float4 w0 = make_float4(nf[ca.x & 15] * am, nf[ca.y & 15] * am,
                                nf[ca.z & 15] * am, nf[ca.w & 15] * am);
        float4 w1 = make_float4(nf[cb.x & 15] * am, nf[cb.y & 15] * am,
                                nf[cb.z & 15] * am, nf[cb.w & 15] * am);
        float4* dst = (float4*)(sm + S_W + bb * WBUF + r * ICH + il0);
        dst[0] = w0; dst[1] = w1;
    }
}

__global__ void __launch_bounds__(NTHR, 1)
qlora_kernel(const float* __restrict__ x,
             const int* __restrict__ codesA, const float* __restrict__ absmaxA,
             const int* __restrict__ codesB, const float* __restrict__ absmaxB,
             float* __restrict__ out)
{
    extern __shared__ float sm[];
    const int tid = threadIdx.x, lane = tid & 31, wid = tid >> 5;

    if (tid < 16) sm[S_NF4 + tid] = c_nf4[tid];
    __syncthreads();   // NF4 table ready before any dequant

    uint32_t sxb = (uint32_t)__cvta_generic_to_shared(sm + S_X);

    int buf = 0;
    int t = blockIdx.x;
    // prologue: produce (t, chunk 0) into buffer 0
    issue_chunk(sm, sxb, x, codesA, absmaxA, t, 0, 0, tid);
    asm volatile("cp.async.commit_group;\n" ::: "memory");

    for (; t < NTILE; t += gridDim.x) {
        unsigned long long a01[RANK], a23[RANK];
        #pragma unroll
        for (int r = 0; r < RANK; r++) { a01[r] = 0ull; a23[r] = 0ull; }

        #pragma unroll 1
        for (int c = 0; c < NCH; c++) {
            // produce next chunk into the other buffer
            int nt = t, nc = c + 1;
            if (nc == NCH) { nc = 0; nt = t + gridDim.x; }
            issue_chunk(sm, sxb, x, codesA, absmaxA, nt, nc, buf ^ 1, tid);
            asm volatile("cp.async.commit_group;\n" ::: "memory");
            asm volatile("cp.async.wait_group 1;\n" ::: "memory");
            __syncthreads();   // current buffer (x cp.async + w STS) visible

            // consume: lane = row, warp covers 32 i's of this chunk, 8 ranks
            const ulonglong2* xp =
                (const ulonglong2*)(sm + S_X + buf * XBUF + lane * XSTR) + wid * 8;
            const ulonglong2* wp =
                (const ulonglong2*)(sm + S_W + buf * WBUF) + wid * 8;
            #pragma unroll
            for (int j = 0; j < 8; j++) {
                ulonglong2 xv = xp[j];                 // 4 x values (conflict-free)
                #pragma unroll
                for (int r = 0; r < RANK; r++) {
                    ulonglong2 wv = wp[r * 128 + j];   // broadcast across warp
                    fma2(a01[r], xv.x, wv.x);
                    fma2(a23[r], xv.y, wv.y);
                }
            }
            __syncthreads();   // all readers done before buffer is overwritten
            buf ^= 1;
        }

        // cross-warp reduce: sRed[wid][row=lane][r]
        {
            float v[RANK];
            #pragma unroll
            for (int r = 0; r < RANK; r++) {
                float2 p = unpk(a01[r]); float2 q = unpk(a23[r]);
                v[r] = (p.x + p.y) + (q.x + q.y);
            }
            float4* dst = (float4*)(sm + S_RED + wid * (TROWS * RANK) + lane * RANK);
            dst[0] = make_float4(v[0], v[1], v[2], v[3]);
            dst[1] = make_float4(v[4], v[5], v[6], v[7]);
        }
        __syncthreads();
        if (tid < TROWS * RANK) {   // 256 threads: sum 16 warp partials
            float s = 0.0f;
            #pragma unroll
            for (int w2 = 0; w2 < 16; w2++)
                s += sm[S_RED + w2 * (TROWS * RANK) + tid];
            sm[S_INT + tid] = s;
        }
        __syncthreads();

        // epilogue: out[row][o] = sum_r interm[row][r] * WB[o][r] * 4
        // (W_B dequantized on the fly; thread owns 8 output cols = 2 float4 groups)
        {
            size_t outbase = (size_t)t * TROWS * OUTDIM;
            #pragma unroll
            for (int og = 0; og < 2; og++) {
                int g = tid + og * NTHR;                       // float4 col group
                float am = 4.0f * __ldg(absmaxB + (g >> 1));   // one block per 2 groups
                int cc[32];
                const int4* cbp = (const int4*)codesB + g * 8; // codes_B[o=4g..4g+3][r]
                #pragma unroll
                for (int q = 0; q < 8; q++) ((int4*)cc)[q] = cbp[q];
                const float* nf = sm + S_NF4;
                unsigned long long wb01[RANK], wb23[RANK];
                #pragma unroll
                for (int r = 0; r < RANK; r++) {
                    float w0 = nf[cc[r] & 15] * am;
                    float w1 = nf[cc[8 + r] & 15] * am;
                    float w2 = nf[cc[16 + r] & 15] * am;
                    float w3 = nf[cc[24 + r] & 15] * am;
                    wb01[r] = pkab(w0, w1);
                    wb23[r] = pkab(w2, w3);
                }
                #pragma unroll 4
                for (int m = 0; m < TROWS; m++) {
                    const float4* ip = (const float4*)(sm + S_INT) + m * 2;
                    float4 s0 = ip[0], s1 = ip[1];          // broadcast
                    float sv[RANK] = { s0.x, s0.y, s0.z, s0.w,
                                       s1.x, s1.y, s1.z, s1.w };
                    unsigned long long o01 = 0ull, o23 = 0ull;
                    #pragma unroll
                    for (int r = 0; r < RANK; r++) {
                        unsigned long long s2 = pk2(sv[r]);
                        fma2(o01, s2, wb01[r]);
                        fma2(o23, s2, wb23[r]);
                    }
                    ulonglong2 ov; ov.x = o01; ov.y = o23;
                    *(ulonglong2*)(out + outbase + (size_t)m * OUTDIM + g * 4) = ov;
                }
            }
        }
    }
}

extern "C" void kernel_launch(void* const* d_in, const int* in_sizes, int n_in,
                              void* d_out, int out_size) {
    const float* x        = (const float*)d_in[0];
    const int*   codes_A  = (const int*)d_in[1];
    const float* absmax_A = (const float*)d_in[2];
    const int*   codes_B  = (const int*)d_in[3];
    const float* absmax_B = (const float*)d_in[4];
    float*       out      = (float*)d_out;
    (void)in_sizes; (void)n_in; (void)out_size;

    int dev = 0, nsm = 148;
    cudaGetDevice(&dev);
    cudaDeviceGetAttribute(&nsm, cudaDevAttrMultiProcessorCount, dev);
    if (nsm > NTILE) nsm = NTILE;

    cudaFuncSetAttribute(qlora_kernel,
                         cudaFuncAttributeMaxDynamicSharedMemorySize, SMEM_BYTES);
    qlora_kernel<<<nsm, NTHR, SMEM_BYTES>>>(x, codes_A, absmax_A,
                                            codes_B, absmax_B, out);
}

// round 7
// speedup vs baseline: 1.2645x; 1.2319x over previous
#include <cuda_runtime.h>
#include <cstdint>
#include <cstddef>

// Fixed problem shapes
#define MROWS  8192           // B*S
#define INDIM  4096
#define OUTDIM 4096
#define RANK   8
#define NTHR   256            // 8 warps per CTA, 2 CTAs per SM
#define TROWS  32             // rows per tile (lane = row)
#define NTILE  (MROWS/TROWS)  // 256
#define ICH    256            // i-chunk size
#define NCH    (INDIM/ICH)    // 16
#define XSTR   260            // padded row stride in smem floats (conflict-free)
#define XBUF   (TROWS*XSTR)   // 8320 floats per x buffer
#define WBUF   (RANK*ICH)     // 2048 floats per w buffer

// smem layout (float offsets)
#define S_X    0                              // 2 x 8320
#define S_W    (2*XBUF)                       // 16640: 2 x 2048
#define S_RED  (S_W + 2*WBUF)                 // 20736: 8 warps x 32 rows x 8
#define S_INT  (S_RED + 8*TROWS*RANK)         // 22784: 32 x 8
#define S_TOT  (S_INT + TROWS*RANK)           // 23040 floats
#define SMEM_BYTES (S_TOT*4)                  // 92160 B  (2 CTAs = 184 KB/SM)

__constant__ float c_nf4[16] = {
    -1.0f, -0.6961928009986877f, -0.5250730514526367f, -0.39491748809814453f,
    -0.28444138169288635f, -0.18477343022823334f, -0.09105003625154495f, 0.0f,
    0.07958029955625534f, 0.16093020141124725f, 0.24611230194568634f,
    0.33791524171829224f, 0.44070982933044434f, 0.5626170039176941f,
    0.7229568362236328f, 1.0f};

// Pre-dequantized weights (scratch __device__ globals; both L2-resident, 128 KB each)
__device__ __align__(16) float g_WA[RANK * INDIM];    // [r][i]
__device__ __align__(16) float g_WBt[RANK * OUTDIM];  // [r][o], pre-scaled by 4.0

__global__ void dequantA_kernel(const int* __restrict__ codes,
                                const float* __restrict__ absmax) {
    int i = blockIdx.x * blockDim.x + threadIdx.x;
    if (i < RANK * INDIM)
        g_WA[i] = c_nf4[codes[i] & 15] * absmax[i >> 6];
}
__global__ void dequantB_kernel(const int* __restrict__ codes,
                                const float* __restrict__ absmax) {
    int i = blockIdx.x * blockDim.x + threadIdx.x;
    if (i < OUTDIM * RANK) {
        int o = i >> 3, r = i & 7;
        g_WBt[r * OUTDIM + o] = 4.0f * c_nf4[codes[i] & 15] * absmax[i >> 6];
    }
}

__device__ __forceinline__ void cp_async16(uint32_t saddr, const void* gptr) {
    asm volatile("cp.async.cg.shared.global [%0], [%1], 16;\n"
                 :: "r"(saddr), "l"(gptr));
}
__device__ __forceinline__ void fma2(unsigned long long& d,
                                     unsigned long long a, unsigned long long b) {
    asm("fma.rn.f32x2 %0, %1, %2, %0;" : "+l"(d) : "l"(a), "l"(b));
}
__device__ __forceinline__ unsigned long long pk2(float v) {
    unsigned long long r; asm("mov.b64 %0, {%1, %1};" : "=l"(r) : "f"(v)); return r;
}
__device__ __forceinline__ unsigned long long pkab(float a, float b) {
    unsigned long long r; asm("mov.b64 %0, {%1, %2};" : "=l"(r) : "f"(a), "f"(b)); return r;
}
__device__ __forceinline__ float2 unpk(unsigned long long v) {
    float2 f; asm("mov.b64 {%0, %1}, %2;" : "=f"(f.x), "=f"(f.y) : "l"(v)); return f;
}

// Producer: pure cp.async — x chunk (32 rows x 256 floats) + W_A chunk (8 x 256).
// No synchronous LDG on the critical path.
__device__ __forceinline__ void issue_chunk(
    uint32_t smb, const float* __restrict__ x,
    int tile, int ch, int bb, int tid)
{
    if (tile >= NTILE) return;
    const float* src = x + (size_t)tile * TROWS * INDIM + (size_t)ch * ICH;
    #pragma unroll
    for (int k = 0; k < 8; k++) {          // 2048 float4 / 256 thr
        int idx = tid + k * NTHR;
        int row = idx >> 6, c4 = idx & 63;
        cp_async16(smb + (uint32_t)((S_X + bb * XBUF + row * XSTR + c4 * 4) * 4),
                   src + (size_t)row * INDIM + c4 * 4);
    }
    const float* wsrc = g_WA + ch * ICH;
    #pragma unroll
    for (int k = 0; k < 2; k++) {          // 512 float4 / 256 thr
        int idx = tid + k * NTHR;
        int r = idx >> 6, c4 = idx & 63;
        cp_async16(smb + (uint32_t)((S_W + bb * WBUF + r * ICH + c4 * 4) * 4),
                   wsrc + (size_t)r * INDIM + c4 * 4);
    }
}

__global__ void __launch_bounds__(NTHR, 2)
qlora_kernel(const float* __restrict__ x, float* __restrict__ out)
{
    extern __shared__ float sm[];
    const int tid = threadIdx.x, lane = tid & 31, wid = tid >> 5;
    uint32_t smb = (uint32_t)__cvta_generic_to_shared(sm);

    int buf = 0;
    int t = blockIdx.x;
    issue_chunk(smb, x, t, 0, 0, tid);
    asm volatile("cp.async.commit_group;\n" ::: "memory");

    for (; t < NTILE; t += gridDim.x) {
        unsigned long long a01[RANK], a23[RANK];
        #pragma unroll
        for (int r = 0; r < RANK; r++) { a01[r] = 0ull; a23[r] = 0ull; }

        #pragma unroll 1
        for (int c = 0; c < NCH; c++) {
            int nt = t, nc = c + 1;
            if (nc == NCH) { nc = 0; nt = t + gridDim.x; }
            issue_chunk(smb, x, nt, nc, buf ^ 1, tid);
            asm volatile("cp.async.commit_group;\n" ::: "memory");
            asm volatile("cp.async.wait_group 1;\n" ::: "memory");
            __syncthreads();   // current buffer complete for all threads

            // lane = row; warp w covers i in [w*32, w*32+32)
            const ulonglong2* xp =
                (const ulonglong2*)(sm + S_X + buf * XBUF + lane * XSTR) + wid * 8;
            const ulonglong2* wp =
                (const ulonglong2*)(sm + S_W + buf * WBUF) + wid * 8;
            #pragma unroll
            for (int j = 0; j < 8; j++) {
                ulonglong2 xv = xp[j];                 // conflict-free (stride 260)
                #pragma unroll
                for (int r = 0; r < RANK; r++) {
                    ulonglong2 wv = wp[r * 64 + j];    // broadcast across warp
                    fma2(a01[r], xv.x, wv.x);
                    fma2(a23[r], xv.y, wv.y);
                }
            }
            __syncthreads();   // readers done before buffer overwrite
            buf ^= 1;
        }

        // cross-warp reduce: 8 warp partials per (row, r)
        {
            float v[RANK];
            #pragma unroll
            for (int r = 0; r < RANK; r++) {
                float2 p = unpk(a01[r]); float2 q = unpk(a23[r]);
                v[r] = (p.x + p.y) + (q.x + q.y);
            }
            float4* dst = (float4*)(sm + S_RED + wid * (TROWS * RANK) + lane * RANK);
            dst[0] = make_float4(v[0], v[1], v[2], v[3]);
            dst[1] = make_float4(v[4], v[5], v[6], v[7]);
        }
        __syncthreads();
        {
            float s = 0.0f;     // all 256 threads: tid = row*8 + r
            #pragma unroll
            for (int w2 = 0; w2 < 8; w2++)
                s += sm[S_RED + w2 * (TROWS * RANK) + tid];
            sm[S_INT + tid] = s;
        }
        __syncthreads();

        // epilogue: thread owns 4 float4 col groups; W_B from L2 (pre-scaled)
        {
            size_t outbase = (size_t)t * TROWS * OUTDIM;
            const float4* gWB4 = (const float4*)g_WBt;
            #pragma unroll
            for (int og = 0; og < 4; og++) {
                int g = tid + og * NTHR;
                unsigned long long wb01[RANK], wb23[RANK];
                #pragma unroll
                for (int r = 0; r < RANK; r++) {
                    float4 w = __ldg(gWB4 + r * (OUTDIM/4) + g);
                    wb01[r] = pkab(w.x, w.y);
                    wb23[r] = pkab(w.z, w.w);
                }
                #pragma unroll 4
                for (int m = 0; m < TROWS; m++) {
                    const float4* ip = (const float4*)(sm + S_INT) + m * 2;
                    float4 s0 = ip[0], s1 = ip[1];   // broadcast LDS
                    float sv[RANK] = { s0.x, s0.y, s0.z, s0.w,
                                       s1.x, s1.y, s1.z, s1.w };
                    unsigned long long o01 = 0ull, o23 = 0ull;
                    #pragma unroll
                    for (int r = 0; r < RANK; r++) {
                        unsigned long long s2 = pk2(sv[r]);
                        fma2(o01, s2, wb01[r]);
                        fma2(o23, s2, wb23[r]);
                    }
                    ulonglong2 ov; ov.x = o01; ov.y = o23;
                    *(ulonglong2*)(out + outbase + (size_t)m * OUTDIM + g * 4) = ov;
                }
            }
        }
    }
}

extern "C" void kernel_launch(void* const* d_in, const int* in_sizes, int n_in,
                              void* d_out, int out_size) {
    const float* x        = (const float*)d_in[0];
    const int*   codes_A  = (const int*)d_in[1];
    const float* absmax_A = (const float*)d_in[2];
    const int*   codes_B  = (const int*)d_in[3];
    const float* absmax_B = (const float*)d_in[4];
    float*       out      = (float*)d_out;
    (void)in_sizes; (void)n_in; (void)out_size;

    dequantA_kernel<<<(RANK * INDIM + 255) / 256, 256>>>(codes_A, absmax_A);
    dequantB_kernel<<<(OUTDIM * RANK + 255) / 256, 256>>>(codes_B, absmax_B);

    int dev = 0, nsm = 148;
    cudaGetDevice(&dev);
    cudaDeviceGetAttribute(&nsm, cudaDevAttrMultiProcessorCount, dev);
    int grid = 2 * nsm;                 // 2 CTAs/SM -> 256 tiles finish in ONE wave
    if (grid > NTILE) grid = NTILE + (NTILE < 2 * nsm ? 0 : 0), grid = 2 * nsm;
    // grid = 2*nsm (304): CTAs with blockIdx.x >= NTILE exit immediately.

    cudaFuncSetAttribute(qlora_kernel,
                         cudaFuncAttributeMaxDynamicSharedMemorySize, SMEM_BYTES);
    qlora_kernel<<<grid, NTHR, SMEM_BYTES>>>(x, out);
}

// round 10
// speedup vs baseline: 1.2973x; 1.0260x over previous
#include <cuda_runtime.h>
#include <cstdint>
#include <cstddef>

// Fixed problem shapes
#define MROWS  8192           // B*S
#define INDIM  4096
#define OUTDIM 4096
#define RANK   8
#define NTHR   256            // 8 warps per CTA, 2 CTAs per SM
#define TROWS  32             // rows per tile (lane = row)
#define NTILE  (MROWS/TROWS)  // 256
#define ICH    128            // i-chunk size
#define NCH    (INDIM/ICH)    // 32
#define NBUF   4              // pipeline depth (3 chunks in flight)
#define XSTR   132            // padded row stride in smem floats (conflict-free)
#define XBUF   (TROWS*XSTR)   // 4224 floats per x buffer
#define WBUF   (RANK*ICH)     // 1024 floats per w buffer

// smem layout (float offsets)
#define S_X    0                              // 4 x 4224 = 16896
#define S_W    (NBUF*XBUF)                    // 16896: 4 x 1024
#define S_RED  (S_W + NBUF*WBUF)              // 20992: 8 warps x 32 rows x 8
#define S_INT  (S_RED + 8*TROWS*RANK)         // 23040: 32 x 8
#define S_TOT  (S_INT + TROWS*RANK)           // 23296 floats
#define SMEM_BYTES (S_TOT*4)                  // 93184 B (2 CTAs = 186 KB/SM)

__constant__ float c_nf4[16] = {
    -1.0f, -0.6961928009986877f, -0.5250730514526367f, -0.39491748809814453f,
    -0.28444138169288635f, -0.18477343022823334f, -0.09105003625154495f, 0.0f,
    0.07958029955625534f, 0.16093020141124725f, 0.24611230194568634f,
    0.33791524171829224f, 0.44070982933044434f, 0.5626170039176941f,
    0.7229568362236328f, 1.0f};

// Pre-dequantized weights (scratch __device__ globals; L2-resident, 128 KB each)
__device__ __align__(16) float g_WA[RANK * INDIM];    // [r][i]
__device__ __align__(16) float g_WBt[RANK * OUTDIM];  // [r][o], pre-scaled by 4.0

// Single merged dequant kernel (one launch instead of two)
__global__ void dequant_kernel(const int* __restrict__ codesA,
                               const float* __restrict__ absmaxA,
                               const int* __restrict__ codesB,
                               const float* __restrict__ absmaxB) {
    int i = blockIdx.x * blockDim.x + threadIdx.x;
    if (i < RANK * INDIM) {
        g_WA[i] = c_nf4[codesA[i] & 15] * absmaxA[i >> 6];
    } else {
        int j = i - RANK * INDIM;
        if (j < OUTDIM * RANK) {
            int o = j >> 3, r = j & 7;
            g_WBt[r * OUTDIM + o] = 4.0f * c_nf4[codesB[j] & 15] * absmaxB[j >> 6];
        }
    }
}

__device__ __forceinline__ void cp_async16(uint32_t saddr, const void* gptr) {
    asm volatile("cp.async.cg.shared.global [%0], [%1], 16;\n"
                 :: "r"(saddr), "l"(gptr));
}
__device__ __forceinline__ void fma2(unsigned long long& d,
                                     unsigned long long a, unsigned long long b) {
    asm("fma.rn.f32x2 %0, %1, %2, %0;" : "+l"(d) : "l"(a), "l"(b));
}
__device__ __forceinline__ unsigned long long pk2(float v) {
    unsigned long long r; asm("mov.b64 %0, {%1, %1};" : "=l"(r) : "f"(v)); return r;
}
__device__ __forceinline__ unsigned long long pkab(float a, float b) {
    unsigned long long r; asm("mov.b64 %0, {%1, %2};" : "=l"(r) : "f"(a), "f"(b)); return r;
}
__device__ __forceinline__ float2 unpk(unsigned long long v) {
    float2 f; asm("mov.b64 {%0, %1}, %2;" : "=f"(f.x), "=f"(f.y) : "l"(v)); return f;
}

// Producer for linear chunk L of this CTA's stream: pure cp.async
// (x: 32 rows x 128 floats = 1024 float4; W_A chunk: 8 x 128 = 256 float4)
__device__ __forceinline__ void issue_chunk(
    uint32_t smb, const float* __restrict__ x,
    int t0, int grid, int L, int tid)
{
    int tile = t0 + (L >> 5) * grid;
    if (tile >= NTILE) return;
    int ch = L & 31;
    int bb = L & (NBUF - 1);
    const float* src = x + (size_t)tile * TROWS * INDIM + (size_t)ch * ICH;
    #pragma unroll
    for (int k = 0; k < 4; k++) {          // 1024 float4 / 256 thr
        int idx = tid + k * NTHR;
        int row = idx >> 5, c4 = idx & 31;
        cp_async16(smb + (uint32_t)((S_X + bb * XBUF + row * XSTR + c4 * 4) * 4),
                   src + (size_t)row * INDIM + c4 * 4);
    }
    {                                       // 256 float4 / 256 thr
        int r = tid >> 5, c4 = tid & 31;
        cp_async16(smb + (uint32_t)((S_W + bb * WBUF + r * ICH + c4 * 4) * 4),
                   g_WA + (size_t)r * INDIM + ch * ICH + c4 * 4);
    }
}

__global__ void __launch_bounds__(NTHR, 2)
qlora_kernel(const float* __restrict__ x, float* __restrict__ out)
{
    extern __shared__ float sm[];
    const int tid = threadIdx.x, lane = tid & 31, wid = tid >> 5;
    const int grid = gridDim.x;
    const int t0 = blockIdx.x;
    if (t0 >= NTILE) return;               // surplus CTAs exit immediately

    uint32_t smb = (uint32_t)__cvta_generic_to_shared(sm);

    // prologue: chunks 0..2 into buffers 0..2, one commit group each
    #pragma unroll
    for (int L = 0; L < NBUF - 1; L++) {
        issue_chunk(smb, x, t0, grid, L, tid);
        asm volatile("cp.async.commit_group;\n" ::: "memory");
    }

    int q = 0;           // next chunk to consume
    int Lh = NBUF - 1;   // next chunk to issue

    for (int t = t0; t < NTILE; t += grid) {
        unsigned long long a01[RANK], a23[RANK];
        #pragma unroll
        for (int r = 0; r < RANK; r++) { a01[r] = 0ull; a23[r] = 0ull; }

        #pragma unroll 1
        for (int c = 0; c < NCH; c++) {
            asm volatile("cp.async.wait_group 2;\n" ::: "memory");
            __syncthreads();   // chunk q visible to all; readers of q-1 retired

            issue_chunk(smb, x, t0, grid, Lh, tid);  // into buffer (q-1)&3
            asm volatile("cp.async.commit_group;\n" ::: "memory");
            Lh++;

            // consume chunk q: lane = row; warp w covers i in [w*16, w*16+16)
            int buf = q & (NBUF - 1);
            const ulonglong2* xp =
                (const ulonglong2*)(sm + S_X + buf * XBUF + lane * XSTR) + wid * 4;
            const ulonglong2* wp =
                (const ulonglong2*)(sm + S_W + buf * WBUF) + wid * 4;
            #pragma unroll
            for (int j = 0; j < 4; j++) {
                ulonglong2 xv = xp[j];                 // conflict-free (stride 132)
                #pragma unroll
                for (int r = 0; r < RANK; r++) {
                    ulonglong2 wv = wp[r * 32 + j];    // broadcast across warp
                    fma2(a01[r], xv.x, wv.x);
                    fma2(a23[r], xv.y, wv.y);
                }
            }
            q++;
        }

        // cross-warp reduce: 8 warp partials per (row, r)
        {
            float v[RANK];
            #pragma unroll
            for (int r = 0; r < RANK; r++) {
                float2 p = unpk(a01[r]); float2 qq = unpk(a23[r]);
                v[r] = (p.x + p.y) + (qq.x + qq.y);
            }
            float4* dst = (float4*)(sm + S_RED + wid * (TROWS * RANK) + lane * RANK);
            dst[0] = make_float4(v[0], v[1], v[2], v[3]);
            dst[1] = make_float4(v[4], v[5], v[6], v[7]);
        }
        __syncthreads();
        {
            float s = 0.0f;     // all 256 threads: tid = row*8 + r
            #pragma unroll
            for (int w2 = 0; w2 < 8; w2++)
                s += sm[S_RED + w2 * (TROWS * RANK) + tid];
            sm[S_INT + tid] = s;
        }
        __syncthreads();

        // epilogue: thread owns 4 float4 col groups; W_B from L2 (pre-scaled)
        {
            size_t outbase = (size_t)t * TROWS * OUTDIM;
            const float4* gWB4 = (const float4*)g_WBt;
            #pragma unroll
            for (int og = 0; og < 4; og++) {
                int g = tid + og * NTHR;
                unsigned long long wb01[RANK], wb23[RANK];
                #pragma unroll
                for (int r = 0; r < RANK; r++) {
                    float4 w = __ldg(gWB4 + r * (OUTDIM/4) + g);
                    wb01[r] = pkab(w.x, w.y);
                    wb23[r] = pkab(w.z, w.w);
                }
                #pragma unroll 4
                for (int m = 0; m < TROWS; m++) {
                    const float4* ip = (const float4*)(sm + S_INT) + m * 2;
                    float4 s0 = ip[0], s1 = ip[1];   // broadcast LDS
                    float sv[RANK] = { s0.x, s0.y, s0.z, s0.w,
                                       s1.x, s1.y, s1.z, s1.w };
                    unsigned long long o01 = 0ull, o23 = 0ull;
                    #pragma unroll
                    for (int r = 0; r < RANK; r++) {
                        unsigned long long s2 = pk2(sv[r]);
                        fma2(o01, s2, wb01[r]);
                        fma2(o23, s2, wb23[r]);
                    }
                    ulonglong2 ov; ov.x = o01; ov.y = o23;
                    *(ulonglong2*)(out + outbase + (size_t)m * OUTDIM + g * 4) = ov;
                }
            }
        }
    }
}

extern "C" void kernel_launch(void* const* d_in, const int* in_sizes, int n_in,
                              void* d_out, int out_size) {
    const float* x        = (const float*)d_in[0];
    const int*   codes_A  = (const int*)d_in[1];
    const float* absmax_A = (const float*)d_in[2];
    const int*   codes_B  = (const int*)d_in[3];
    const float* absmax_B = (const float*)d_in[4];
    float*       out      = (float*)d_out;
    (void)in_sizes; (void)n_in; (void)out_size;

    // single dequant launch covering both A (32768) and B (32768)
    dequant_kernel<<<(2 * RANK * INDIM + 255) / 256, 256>>>(
        codes_A, absmax_A, codes_B, absmax_B);

    int dev = 0, nsm = 148;
    cudaGetDevice(&dev);
    cudaDeviceGetAttribute(&nsm, cudaDevAttrMultiProcessorCount, dev);
    int grid = 2 * nsm;   // 2 CTAs/SM; 256 working CTAs finish in one wave

    cudaFuncSetAttribute(qlora_kernel,
                         cudaFuncAttributeMaxDynamicSharedMemorySize, SMEM_BYTES);
    qlora_kernel<<<grid, NTHR, SMEM_BYTES>>>(x, out);
}